// round 16
// baseline (speedup 1.0000x reference)
#include <cuda_runtime.h>
#include <cuda_fp16.h>

#define N_ 16
#define C_ 64
#define H_ 64
#define W_ 64

// ---- static device scratch (allocation-free) ------------------------------
__device__ __align__(16) float g_t4[N_ * C_ * H_ * W_];          // 16 MB
// fp16 conv weights: [tap(49)][chunk(2)][co(64)][32 halves interleaved], negated
__device__ __align__(16) __half g_wt16[49 * 2 * 64 * 32];        // 401 KB
// fp16 w8 weights:   [chunk(2)][co(64)][32 halves interleaved]  (not negated)
__device__ __align__(16) __half g_w8t16[2 * 64 * 32];            // 16 KB

#define MMA_F16(D, a0,a1,a2,a3, b0,b1)                                        \
    asm volatile("mma.sync.aligned.m16n8k16.row.col.f32.f16.f16.f32 "         \
        "{%0,%1,%2,%3}, {%4,%5,%6,%7}, {%8,%9}, {%0,%1,%2,%3};"               \
        : "+f"(D[0]), "+f"(D[1]), "+f"(D[2]), "+f"(D[3])                      \
        : "r"(a0), "r"(a1), "r"(a2), "r"(a3), "r"(b0), "r"(b1))

// interleave position of k (0..31) inside a 32-halve row:
// step s = k/16, kk = k%16; c-block of 4: [2c,2c+1,2c+8,2c+9]; p = 8c+4s+sub
__device__ __forceinline__ int frag_pos32(int k) {
    int s  = k >> 4;
    int kk = k & 15;
    int c  = (kk & 7) >> 1;
    int sub = (kk < 8) ? (kk & 1) : (2 | (kk & 1));
    return 8 * c + 4 * s + sub;
}

// ---------------------------------------------------------------------------
// Weight transpose/negate (w4) + transpose (w8) into fp16 fragment layout.
// ---------------------------------------------------------------------------
__global__ void wtrans_kernel(const float* __restrict__ w4,
                              const float* __restrict__ w8)
{
    int idx = blockIdx.x * 256 + threadIdx.x;
    if (idx < 49 * 2 * 64 * 32) {
        int k     = idx & 31;
        int co    = (idx >> 5) & 63;
        int chunk = (idx >> 11) & 1;
        int tap   = idx >> 12;
        int ci    = chunk * 32 + k;
        float v = -w4[co * 3136 + ci * 49 + tap];
        g_wt16[(size_t)((tap * 2 + chunk) * 64 + co) * 32 + frag_pos32(k)] = __float2half(v);
    } else if (idx < 49 * 2 * 64 * 32 + 2 * 64 * 32) {
        int i2    = idx - 49 * 2 * 64 * 32;
        int k     = i2 & 31;
        int co    = (i2 >> 5) & 63;
        int chunk = i2 >> 11;
        float v = w8[co * 64 + chunk * 32 + k];
        g_w8t16[(size_t)(chunk * 64 + co) * 32 + frag_pos32(k)] = __float2half(v);
    }
}

// ---------------------------------------------------------------------------
// Conv 7x7 via fp16 tensor cores. Block: 256 thr, tile co64 x (2 rows x 64 w).
// Grid (32, 16). A fragments from L2, SOFTWARE-PIPELINED one tap ahead.
// Vectorized halo fill (float4 over w). SMEM: halo only (35.8KB).
// ---------------------------------------------------------------------------
#define HALO_HALVES (8 * 70 * 32)      // 17920

__global__ __launch_bounds__(256, 2)
void conv7x7_mma_kernel(const float* __restrict__ x)
{
    __shared__ __align__(16) __half halo[HALO_HALVES];

    const int tid    = threadIdx.x;
    const int warp   = tid >> 5;
    const int lane   = tid & 31;
    const int warp_m = warp >> 1;     // 0..3 : co slice of 16
    const int warp_r = warp & 1;      // 0..1 : output row within tile
    const int g      = lane >> 2;     // 0..7
    const int c      = lane & 3;      // 0..3

    const int n  = blockIdx.y;
    const int h0 = blockIdx.x * 2;    // two output rows per block

    float d[8][4];
    #pragma unroll
    for (int j = 0; j < 8; j++)
        #pragma unroll
        for (int k = 0; k < 4; k++) d[j][k] = 0.0f;

    const int coA = warp_m * 16 + g;
    const __half* wA0 = g_wt16 + coA * 32 + c * 8;         // row coA
    const __half* wA1 = g_wt16 + (coA + 8) * 32 + c * 8;   // row coA+8

    for (int chunk = 0; chunk < 2; chunk++) {
        __syncthreads();   // previous chunk readers done before halo overwrite

        float4* hz = (float4*)halo;
        for (int i = tid; i < HALO_HALVES / 8; i += 256)
            hz[i] = make_float4(0.f, 0.f, 0.f, 0.f);
        __syncthreads();

        // ---- fill halo (vectorized: 4 consecutive w per iteration) ----
        for (int i = tid; i < 8 * 16 * 32; i += 256) {
            int w4i = i & 15;              // group of 4 w
            int cl  = (i >> 4) & 31;
            int r   = i >> 9;              // 0..7
            int gh  = h0 - 3 + r;
            if ((unsigned)gh < (unsigned)H_) {
                float4 v = *(const float4*)&x[((n * C_ + chunk * 32 + cl) * H_ + gh) * W_ + w4i * 4];
                int p = frag_pos32(cl);
                int base = (r * 70 + w4i * 4 + 3) * 32 + p;
                halo[base]          = __float2half(v.x);
                halo[base + 32]     = __float2half(v.y);
                halo[base + 64]     = __float2half(v.z);
                halo[base + 96]     = __float2half(v.w);
            }
        }
        __syncthreads();   // halo visible

        // ---- tap loop, A fragments pipelined one tap ahead ----
        const size_t cbase = (size_t)chunk * 64 * 32;
        uint4 A0n = *(const uint4*)(wA0 + cbase);          // tap 0
        uint4 A1n = *(const uint4*)(wA1 + cbase);
        int kh = 0, kw = 0;
        #pragma unroll 1
        for (int tap = 0; tap < 49; tap++) {
            uint4 A0c = A0n, A1c = A1n;
            if (tap < 48) {
                const size_t toff = (size_t)(((tap + 1) * 2 + chunk) * 64) * 32;
                A0n = *(const uint4*)(wA0 + toff);
                A1n = *(const uint4*)(wA1 + toff);
            }
            const __half* hb = halo + ((kh + warp_r) * 70 + g + kw) * 32 + c * 8;
            #pragma unroll
            for (int j = 0; j < 8; j++) {
                uint4 B = *(const uint4*)(hb + j * (8 * 32));
                MMA_F16(d[j], A0c.x, A1c.x, A0c.y, A1c.y, B.x, B.y);   // k-step 0
                MMA_F16(d[j], A0c.z, A1c.z, A0c.w, A1c.w, B.z, B.w);   // k-step 1
            }
            if (++kw == 7) { kw = 0; ++kh; }
        }
    }

    // ---- store t4 tile (row h0 + warp_r, full 64 px) ----
    const int hrow_o = h0 + warp_r;
    #pragma unroll
    for (int j = 0; j < 8; j++) {
        int wcol = j * 8 + 2 * c;
        #pragma unroll
        for (int s = 0; s < 2; s++) {
            int co = coA + s * 8;
            float2 v = make_float2(d[j][s * 2], d[j][s * 2 + 1]);
            *(float2*)&g_t4[((n * C_ + co) * H_ + hrow_o) * W_ + wcol] = v;
        }
    }
}

// ---------------------------------------------------------------------------
// MMA-based fuse kernel: out = x * (w5 ⊛ t4) + w8 @ roll(x,1,H).
// t4 tile register-staged (LDGs fly during xroll chunk-0 fill), then STS.
// ---------------------------------------------------------------------------
#define T4S_STRIDE  68                          // fp32 words per (row,co) line
#define T4S_WORDS   (2 * 64 * T4S_STRIDE)       // 8704 words = 34816 B
#define XROLL_WORDS (2 * 64 * 32 / 2)           // 2048 fp32 words = 8192 B

__global__ __launch_bounds__(256)
void fuse_mma_kernel(const float* __restrict__ x,
                     const float* __restrict__ w5,
                     float* __restrict__ out)
{
    __shared__ __align__(16) float smemf[T4S_WORDS + XROLL_WORDS];

    const int tid    = threadIdx.x;
    const int warp   = tid >> 5;
    const int lane   = tid & 31;
    const int warp_m = warp >> 1;     // 0..3 : co slice of 16
    const int warp_r = warp & 1;      // 0..1 : output row within tile
    const int g      = lane >> 2;     // 0..7
    const int c      = lane & 3;      // 0..3

    const int n  = blockIdx.y;
    const int h0 = blockIdx.x * 2;

    float*  t4s   = smemf;
    __half* xroll = (__half*)(smemf + T4S_WORDS);

    // ---- issue t4 tile loads into registers (latency overlapped below) ----
    float4 t4r[8];
    #pragma unroll
    for (int kreg = 0; kreg < 8; kreg++) {
        int idx = tid + kreg * 256;
        int q  = idx & 15;
        int co = (idx >> 4) & 63;
        int r  = idx >> 10;
        t4r[kreg] = *(const float4*)&g_t4[((n * C_ + co) * H_ + h0 + r) * W_ + q * 4];
    }

    // ---- fill xroll chunk 0 while t4 loads are in flight ----
    for (int i = tid; i < 2 * 16 * 32; i += 256) {
        int w4i = i & 15;
        int cl  = (i >> 4) & 31;
        int r   = i >> 9;              // 0..1
        int gh  = (h0 + r + H_ - 1) & (H_ - 1);
        float4 v = *(const float4*)&x[((n * C_ + cl) * H_ + gh) * W_ + w4i * 4];
        int p = frag_pos32(cl);
        int base = (r * 64 + w4i * 4) * 32 + p;
        xroll[base]      = __float2half(v.x);
        xroll[base + 32] = __float2half(v.y);
        xroll[base + 64] = __float2half(v.z);
        xroll[base + 96] = __float2half(v.w);
    }

    // ---- store t4 registers to SMEM ----
    #pragma unroll
    for (int kreg = 0; kreg < 8; kreg++) {
        int idx = tid + kreg * 256;
        int q  = idx & 15;
        int co = (idx >> 4) & 63;
        int r  = idx >> 10;
        *(float4*)&t4s[(r * 64 + co) * T4S_STRIDE + q * 4] = t4r[kreg];
    }
    __syncthreads();   // xroll chunk 0 + t4s visible

    // ---- t8 accumulation ----
    float d8[8][4];
    #pragma unroll
    for (int j = 0; j < 8; j++)
        #pragma unroll
        for (int k = 0; k < 4; k++) d8[j][k] = 0.0f;

    const int coA = warp_m * 16 + g;

    for (int chunk = 0; chunk < 2; chunk++) {
        if (chunk == 1) {
            __syncthreads();   // chunk-0 xroll reads done
            for (int i = tid; i < 2 * 16 * 32; i += 256) {
                int w4i = i & 15;
                int cl  = (i >> 4) & 31;
                int r   = i >> 9;
                int gh  = (h0 + r + H_ - 1) & (H_ - 1);
                float4 v = *(const float4*)&x[((n * C_ + 32 + cl) * H_ + gh) * W_ + w4i * 4];
                int p = frag_pos32(cl);
                int base = (r * 64 + w4i * 4) * 32 + p;
                xroll[base]      = __float2half(v.x);
                xroll[base + 32] = __float2half(v.y);
                xroll[base + 64] = __float2half(v.z);
                xroll[base + 96] = __float2half(v.w);
            }
            __syncthreads();   // xroll chunk 1 visible
        }

        const size_t w8off = (size_t)(chunk * 64) * 32;
        uint4 A0 = *(const uint4*)(g_w8t16 + coA * 32 + c * 8 + w8off);
        uint4 A1 = *(const uint4*)(g_w8t16 + (coA + 8) * 32 + c * 8 + w8off);
        const __half* xb = xroll + (warp_r * 64 + g) * 32 + c * 8;
        #pragma unroll
        for (int j = 0; j < 8; j++) {
            uint4 B = *(const uint4*)(xb + j * (8 * 32));
            MMA_F16(d8[j], A0.x, A1.x, A0.y, A1.y, B.x, B.y);
            MMA_F16(d8[j], A0.z, A1.z, A0.w, A1.w, B.z, B.w);
        }
    }

    // ---- epilogue: out = x * (w5 ⊛ t4) + t8 ----
    const int hrow = h0 + warp_r;
    #pragma unroll
    for (int s = 0; s < 2; s++) {
        const int co = coA + s * 8;
        const float a0 = w5[co * 3 + 0];
        const float a1 = w5[co * 3 + 1];
        const float a2 = w5[co * 3 + 2];
        const float* t4line = t4s + (warp_r * 64 + co) * T4S_STRIDE;
        const float* xline  = x   + ((n * C_ + co) * H_ + hrow) * W_;
        float*       oline  = out + ((size_t)((n * C_ + co) * H_ + hrow)) * W_;
        #pragma unroll
        for (int j = 0; j < 8; j++) {
            const int w0 = j * 8 + 2 * c;
            float r2[2];
            #pragma unroll
            for (int e = 0; e < 2; e++) {
                const int w = w0 + e;
                float tm = (w >= 2)      ? t4line[w - 2] : 0.0f;
                float tc = t4line[w];
                float tp = (w <= W_ - 3) ? t4line[w + 2] : 0.0f;
                float t5 = a0 * tm + a1 * tc + a2 * tp;
                r2[e] = xline[w] * t5 + d8[j][s * 2 + e];
            }
            *(float2*)&oline[w0] = make_float2(r2[0], r2[1]);
        }
    }
}

// ---------------------------------------------------------------------------
extern "C" void kernel_launch(void* const* d_in, const int* in_sizes, int n_in,
                              void* d_out, int out_size)
{
    const float* x  = (const float*)d_in[0];   // (16,64,64,64)
    const float* w4 = (const float*)d_in[1];   // (64,64,7,7)
    const float* w5 = (const float*)d_in[2];   // (64,1,1,3)
    const float* w8 = (const float*)d_in[3];   // (64,64,1,1)
    float* out = (float*)d_out;

    wtrans_kernel<<<800, 256>>>(w4, w8);

    dim3 g1(H_ / 2, N_);             // (32, 16)
    conv7x7_mma_kernel<<<g1, 256>>>(x);

    dim3 g2(H_ / 2, N_);             // (32, 16)
    fuse_mma_kernel<<<g2, 256>>>(x, w5, out);
}

// round 17
// speedup vs baseline: 1.0310x; 1.0310x over previous
#include <cuda_runtime.h>
#include <cuda_fp16.h>

#define N_ 16
#define C_ 64
#define H_ 64
#define W_ 64

// ---- static device scratch (allocation-free) ------------------------------
__device__ __align__(16) float g_t4[N_ * C_ * H_ * W_];          // 16 MB
// fp16 conv weights: [tap(49)][chunk(2)][co(64)][32 halves interleaved], negated
__device__ __align__(16) __half g_wt16[49 * 2 * 64 * 32];        // 401 KB
// fp16 w8 weights:   [chunk(2)][co(64)][32 halves interleaved]  (not negated)
__device__ __align__(16) __half g_w8t16[2 * 64 * 32];            // 16 KB

#define MMA_F16(D, a0,a1,a2,a3, b0,b1)                                        \
    asm volatile("mma.sync.aligned.m16n8k16.row.col.f32.f16.f16.f32 "         \
        "{%0,%1,%2,%3}, {%4,%5,%6,%7}, {%8,%9}, {%0,%1,%2,%3};"               \
        : "+f"(D[0]), "+f"(D[1]), "+f"(D[2]), "+f"(D[3])                      \
        : "r"(a0), "r"(a1), "r"(a2), "r"(a3), "r"(b0), "r"(b1))

// interleave position of k (0..31) inside a 32-halve row:
// step s = k/16, kk = k%16; c-block of 4: [2c,2c+1,2c+8,2c+9]; p = 8c+4s+sub
__device__ __forceinline__ int frag_pos32(int k) {
    int s  = k >> 4;
    int kk = k & 15;
    int c  = (kk & 7) >> 1;
    int sub = (kk < 8) ? (kk & 1) : (2 | (kk & 1));
    return 8 * c + 4 * s + sub;
}

// ---------------------------------------------------------------------------
// Weight transpose/negate (w4) + transpose (w8) into fp16 fragment layout.
// ---------------------------------------------------------------------------
__global__ void wtrans_kernel(const float* __restrict__ w4,
                              const float* __restrict__ w8)
{
    int idx = blockIdx.x * 256 + threadIdx.x;
    if (idx < 49 * 2 * 64 * 32) {
        int k     = idx & 31;
        int co    = (idx >> 5) & 63;
        int chunk = (idx >> 11) & 1;
        int tap   = idx >> 12;
        int ci    = chunk * 32 + k;
        float v = -w4[co * 3136 + ci * 49 + tap];
        g_wt16[(size_t)((tap * 2 + chunk) * 64 + co) * 32 + frag_pos32(k)] = __float2half(v);
    } else if (idx < 49 * 2 * 64 * 32 + 2 * 64 * 32) {
        int i2    = idx - 49 * 2 * 64 * 32;
        int k     = i2 & 31;
        int co    = (i2 >> 5) & 63;
        int chunk = i2 >> 11;
        float v = w8[co * 64 + chunk * 32 + k];
        g_w8t16[(size_t)(chunk * 64 + co) * 32 + frag_pos32(k)] = __float2half(v);
    }
}

// ---------------------------------------------------------------------------
// Conv 7x7 via fp16 tensor cores. Block: 256 thr, tile co64 x (2 rows x 64 w).
// Grid (32, 16). Warp remap: warp = (co-half, row, w-half); each warp does
// M=32 (2 A-tiles) x N=32 (4 n-tiles) -> B-fragment LDS traffic HALVED.
// A fragments from L2 (LDG.128). SMEM: halo only (35.8KB).
// ---------------------------------------------------------------------------
#define HALO_HALVES (8 * 70 * 32)      // 17920

__global__ __launch_bounds__(256)
void conv7x7_mma_kernel(const float* __restrict__ x)
{
    __shared__ __align__(16) __half halo[HALO_HALVES];

    const int tid    = threadIdx.x;
    const int warp   = tid >> 5;
    const int lane   = tid & 31;
    const int warp_c = warp >> 2;          // 0..1 : co half (32 co)
    const int warp_r = (warp >> 1) & 1;    // 0..1 : output row within tile
    const int warp_h = warp & 1;           // 0..1 : w half (32 px)
    const int g      = lane >> 2;          // 0..7
    const int c      = lane & 3;           // 0..3

    const int n  = blockIdx.y;
    const int h0 = blockIdx.x * 2;    // two output rows per block

    float d[2][4][4];                 // [co-tile][n-tile][reg]
    #pragma unroll
    for (int t = 0; t < 2; t++)
        #pragma unroll
        for (int j = 0; j < 4; j++)
            #pragma unroll
            for (int k = 0; k < 4; k++) d[t][j][k] = 0.0f;

    // A-fragment row pointers: co tiles warp_c*32 + {0,16}, rows +g / +g+8
    const __half* wA[2][2];
    #pragma unroll
    for (int t = 0; t < 2; t++) {
        int m = warp_c * 32 + t * 16;
        wA[t][0] = g_wt16 + (m + g) * 32 + c * 8;
        wA[t][1] = g_wt16 + (m + g + 8) * 32 + c * 8;
    }

    for (int chunk = 0; chunk < 2; chunk++) {
        __syncthreads();   // previous chunk readers done before halo overwrite

        float4* hz = (float4*)halo;
        for (int i = tid; i < HALO_HALVES / 8; i += 256)
            hz[i] = make_float4(0.f, 0.f, 0.f, 0.f);
        __syncthreads();

        for (int i = tid; i < 8 * 64 * 32; i += 256) {
            int w  = i & 63;
            int cl = (i >> 6) & 31;
            int r  = i >> 11;              // 0..7
            int gh = h0 - 3 + r;
            if ((unsigned)gh < (unsigned)H_) {
                float v = x[((n * C_ + chunk * 32 + cl) * H_ + gh) * W_ + w];
                halo[(r * 70 + w + 3) * 32 + frag_pos32(cl)] = __float2half(v);
            }
        }
        __syncthreads();   // halo visible

        #pragma unroll 1
        for (int kh = 0; kh < 7; kh++) {
            const __half* hrow = halo + ((kh + warp_r) * 70 + warp_h * 32 + g) * 32 + c * 8;
            #pragma unroll
            for (int kw = 0; kw < 7; kw++) {
                const int tap = kh * 7 + kw;
                const size_t toff = (size_t)((tap * 2 + chunk) * 64) * 32;
                uint4 A00 = *(const uint4*)(wA[0][0] + toff);
                uint4 A01 = *(const uint4*)(wA[0][1] + toff);
                uint4 A10 = *(const uint4*)(wA[1][0] + toff);
                uint4 A11 = *(const uint4*)(wA[1][1] + toff);

                const __half* hb = hrow + kw * 32;
                #pragma unroll
                for (int j = 0; j < 4; j++) {
                    uint4 B = *(const uint4*)(hb + j * (8 * 32));
                    MMA_F16(d[0][j], A00.x, A01.x, A00.y, A01.y, B.x, B.y);
                    MMA_F16(d[0][j], A00.z, A01.z, A00.w, A01.w, B.z, B.w);
                    MMA_F16(d[1][j], A10.x, A11.x, A10.y, A11.y, B.x, B.y);
                    MMA_F16(d[1][j], A10.z, A11.z, A10.w, A11.w, B.z, B.w);
                }
            }
        }
    }

    // ---- store t4 tile (row h0 + warp_r, w half warp_h) ----
    const int hrow_o = h0 + warp_r;
    #pragma unroll
    for (int t = 0; t < 2; t++) {
        #pragma unroll
        for (int j = 0; j < 4; j++) {
            int wcol = warp_h * 32 + j * 8 + 2 * c;
            #pragma unroll
            for (int s = 0; s < 2; s++) {
                int co = warp_c * 32 + t * 16 + g + s * 8;
                float2 v = make_float2(d[t][j][s * 2], d[t][j][s * 2 + 1]);
                *(float2*)&g_t4[((n * C_ + co) * H_ + hrow_o) * W_ + wcol] = v;
            }
        }
    }
}

// ---------------------------------------------------------------------------
// MMA-based fuse kernel (R15 version, unchanged):
// out = x * (w5 ⊛ t4) + w8 @ roll(x,1,H).
// ---------------------------------------------------------------------------
#define T4S_STRIDE  68                          // fp32 words per (row,co) line
#define T4S_WORDS   (2 * 64 * T4S_STRIDE)       // 8704 words = 34816 B
#define XROLL_WORDS (2 * 64 * 32 / 2)           // 2048 fp32 words = 8192 B

__global__ __launch_bounds__(256)
void fuse_mma_kernel(const float* __restrict__ x,
                     const float* __restrict__ w5,
                     float* __restrict__ out)
{
    __shared__ __align__(16) float smemf[T4S_WORDS + XROLL_WORDS];

    const int tid    = threadIdx.x;
    const int warp   = tid >> 5;
    const int lane   = tid & 31;
    const int warp_m = warp >> 1;     // 0..3 : co slice of 16
    const int warp_r = warp & 1;      // 0..1 : output row within tile
    const int g      = lane >> 2;     // 0..7
    const int c      = lane & 3;      // 0..3

    const int n  = blockIdx.y;
    const int h0 = blockIdx.x * 2;

    float*  t4s   = smemf;
    __half* xroll = (__half*)(smemf + T4S_WORDS);

    // ---- stage t4 tile: 2 rows x 64 co x 64 w, coalesced float4 loads ----
    for (int i = tid; i < 2 * 64 * 16; i += 256) {
        int q  = i & 15;           // float4 index within 64-w line
        int co = (i >> 4) & 63;
        int r  = i >> 10;          // 0..1
        float4 v = *(const float4*)&g_t4[((n * C_ + co) * H_ + h0 + r) * W_ + q * 4];
        *(float4*)&t4s[(r * 64 + co) * T4S_STRIDE + q * 4] = v;
    }

    // ---- t8 accumulation: 2 chunks of fp16 MMA on rolled x ----
    float d8[8][4];
    #pragma unroll
    for (int j = 0; j < 8; j++)
        #pragma unroll
        for (int k = 0; k < 4; k++) d8[j][k] = 0.0f;

    const int coA = warp_m * 16 + g;

    for (int chunk = 0; chunk < 2; chunk++) {
        __syncthreads();   // prev chunk xroll reads done (also orders t4s stores)

        for (int i = tid; i < 2 * 64 * 32; i += 256) {
            int w  = i & 63;
            int cl = (i >> 6) & 31;
            int r  = i >> 11;              // 0..1
            int gh = (h0 + r + H_ - 1) & (H_ - 1);
            float v = x[((n * C_ + chunk * 32 + cl) * H_ + gh) * W_ + w];
            xroll[(r * 64 + w) * 32 + frag_pos32(cl)] = __float2half(v);
        }
        __syncthreads();   // xroll visible (and t4s visible after 1st sync)

        const size_t w8off = (size_t)(chunk * 64) * 32;
        uint4 A0 = *(const uint4*)(g_w8t16 + coA * 32 + c * 8 + w8off);
        uint4 A1 = *(const uint4*)(g_w8t16 + (coA + 8) * 32 + c * 8 + w8off);
        const __half* xb = xroll + (warp_r * 64 + g) * 32 + c * 8;
        #pragma unroll
        for (int j = 0; j < 8; j++) {
            uint4 B = *(const uint4*)(xb + j * (8 * 32));
            MMA_F16(d8[j], A0.x, A1.x, A0.y, A1.y, B.x, B.y);
            MMA_F16(d8[j], A0.z, A1.z, A0.w, A1.w, B.z, B.w);
        }
    }

    // ---- epilogue: out = x * (w5 ⊛ t4) + t8 ----
    const int hrow = h0 + warp_r;
    #pragma unroll
    for (int s = 0; s < 2; s++) {
        const int co = coA + s * 8;
        const float a0 = w5[co * 3 + 0];
        const float a1 = w5[co * 3 + 1];
        const float a2 = w5[co * 3 + 2];
        const float* t4line = t4s + (warp_r * 64 + co) * T4S_STRIDE;
        const float* xline  = x   + ((n * C_ + co) * H_ + hrow) * W_;
        float*       oline  = out + ((size_t)((n * C_ + co) * H_ + hrow)) * W_;
        #pragma unroll
        for (int j = 0; j < 8; j++) {
            const int w0 = j * 8 + 2 * c;
            float r2[2];
            #pragma unroll
            for (int e = 0; e < 2; e++) {
                const int w = w0 + e;
                float tm = (w >= 2)      ? t4line[w - 2] : 0.0f;
                float tc = t4line[w];
                float tp = (w <= W_ - 3) ? t4line[w + 2] : 0.0f;
                float t5 = a0 * tm + a1 * tc + a2 * tp;
                r2[e] = xline[w] * t5 + d8[j][s * 2 + e];
            }
            *(float2*)&oline[w0] = make_float2(r2[0], r2[1]);
        }
    }
}

// ---------------------------------------------------------------------------
extern "C" void kernel_launch(void* const* d_in, const int* in_sizes, int n_in,
                              void* d_out, int out_size)
{
    const float* x  = (const float*)d_in[0];   // (16,64,64,64)
    const float* w4 = (const float*)d_in[1];   // (64,64,7,7)
    const float* w5 = (const float*)d_in[2];   // (64,1,1,3)
    const float* w8 = (const float*)d_in[3];   // (64,64,1,1)
    float* out = (float*)d_out;

    wtrans_kernel<<<800, 256>>>(w4, w8);

    dim3 g1(H_ / 2, N_);             // (32, 16)
    conv7x7_mma_kernel<<<g1, 256>>>(x);

    dim3 g2(H_ / 2, N_);             // (32, 16)
    fuse_mma_kernel<<<g2, 256>>>(x, w5, out);
}